// round 6
// baseline (speedup 1.0000x reference)
#include <cuda_runtime.h>
#include <cstdint>

// Problem constants
#define BATCH 4
#define SEQ   2048
#define EMB   1024
#define HDIM  1024

// Tiling
#define BM 128
#define BN 128
#define BK 16
#define NTHREADS 256
#define STAGES 3

#define AS_STRIDE 20    // 16 + 4 pad (floats) -> conflict-free frag loads
#define VS_STRIDE 136   // 128 + 8 pad (floats) -> conflict-free frag loads

#define AS_FLOATS (BM * AS_STRIDE)      // 2560 floats per stage
#define VS_FLOATS (BK * VS_STRIDE)      // 2176 floats per stage

// Scratch (static device allocations; no runtime allocs allowed)
__device__ float g_qkv[3][(size_t)BATCH * SEQ * EMB];    // Q, K, V (tf32-rounded)
__device__ float g_p[(size_t)BATCH * SEQ * SEQ];          // scores / probs
__device__ float g_xtf[(size_t)BATCH * SEQ * HDIM];       // tf32-rounded x
__device__ float g_wtf[3][(size_t)EMB * HDIM];            // tf32-rounded weights

// ---------------------------------------------------------------------------
// PTX helpers
// ---------------------------------------------------------------------------
__device__ __forceinline__ uint32_t f2tf(float x) {
    uint32_t r;
    asm("cvt.rna.tf32.f32 %0, %1;" : "=r"(r) : "f"(x));
    return r;
}
__device__ __forceinline__ float f2tff(float x) { return __uint_as_float(f2tf(x)); }

__device__ __forceinline__ void mma8(float* c, const uint32_t* a,
                                     uint32_t b0, uint32_t b1) {
    asm volatile(
        "mma.sync.aligned.m16n8k8.row.col.f32.tf32.tf32.f32 "
        "{%0,%1,%2,%3}, {%4,%5,%6,%7}, {%8,%9}, {%0,%1,%2,%3};"
        : "+f"(c[0]), "+f"(c[1]), "+f"(c[2]), "+f"(c[3])
        : "r"(a[0]), "r"(a[1]), "r"(a[2]), "r"(a[3]), "r"(b0), "r"(b1));
}

__device__ __forceinline__ void cp16(uint32_t dst, const float* src) {
    asm volatile("cp.async.ca.shared.global [%0], [%1], 16;" :: "r"(dst), "l"(src));
}
__device__ __forceinline__ void cp_commit() { asm volatile("cp.async.commit_group;"); }
template <int N>
__device__ __forceinline__ void cp_wait() { asm volatile("cp.async.wait_group %0;" :: "n"(N)); }

// ---------------------------------------------------------------------------
// Kernel 0: elementwise tf32 rounding of x / W into scratch.
// which: 0 -> g_xtf, 1..3 -> g_wtf[which-1]
// ---------------------------------------------------------------------------
__global__ void __launch_bounds__(NTHREADS)
cvt_kernel(const float4* __restrict__ src, int which, int n4)
{
    float* dstf = (which == 0) ? g_xtf : g_wtf[which - 1];
    float4* dst = (float4*)dstf;
    int i = blockIdx.x * NTHREADS + threadIdx.x;
    if (i < n4) {
        float4 v = src[i];
        v.x = f2tff(v.x); v.y = f2tff(v.y); v.z = f2tff(v.z); v.w = f2tff(v.w);
        dst[i] = v;
    }
}

// ---------------------------------------------------------------------------
// Kernel 1: QKV projection. out[m][e] = sum_h x[m][h]*W[e][h] + bias[e]
// NT GEMM on pre-rounded tf32 data. grid.z selects Q/K/V.
// Dynamic smem: STAGES * (As + Bs) = 3 * 2 * 2560 floats = 61440 B
// ---------------------------------------------------------------------------
__global__ void __launch_bounds__(NTHREADS, 2)
qkv_kernel(const float* __restrict__ bi0,
           const float* __restrict__ bi1,
           const float* __restrict__ bi2)
{
    extern __shared__ float smem[];
    float* As = smem;                       // [STAGES][AS_FLOATS]
    float* Bs = smem + STAGES * AS_FLOATS;  // [STAGES][AS_FLOATS]

    const int which = blockIdx.z;
    const float* x    = g_xtf;
    const float* W    = g_wtf[which];
    const float* bias = (which == 0) ? bi0 : (which == 1) ? bi1 : bi2;
    float* out = g_qkv[which];

    const int m0 = blockIdx.y * BM, n0 = blockIdx.x * BN;
    const int tid = threadIdx.x;
    const int warp = tid >> 5, lane = tid & 31;
    const int wm = warp & 1, wn = warp >> 1;
    const int g = lane >> 2, tig = lane & 3;

    const int ar = tid >> 2, ac = (tid & 3) * 4;
    const float* ag = x + (size_t)(m0 + ar) * HDIM + ac;
    const float* bg = W + (size_t)(n0 + ar) * HDIM + ac;
    const uint32_t asw = (uint32_t)__cvta_generic_to_shared(As) + (ar * AS_STRIDE + ac) * 4;
    const uint32_t bsw = (uint32_t)__cvta_generic_to_shared(Bs) + (ar * AS_STRIDE + ac) * 4;
    const uint32_t BUF = AS_FLOATS * 4;
    const uint32_t ROWS64 = 64 * AS_STRIDE * 4;

    float acc[4][4][4];
#pragma unroll
    for (int i = 0; i < 4; i++)
#pragma unroll
        for (int j = 0; j < 4; j++)
#pragma unroll
            for (int k = 0; k < 4; k++) acc[i][j][k] = 0.f;

    auto prefetch = [&](int t, int s) {
        const float* a2 = ag + t * BK;
        const float* b2 = bg + t * BK;
        const uint32_t off = s * BUF;
        cp16(asw + off, a2);  cp16(asw + off + ROWS64, a2 + (size_t)64 * HDIM);
        cp16(bsw + off, b2);  cp16(bsw + off + ROWS64, b2 + (size_t)64 * HDIM);
        cp_commit();
    };

    const int T = HDIM / BK;
    prefetch(0, 0);
    prefetch(1, 1);

    for (int t = 0; t < T; ++t) {
        if (t + 1 < T) cp_wait<1>(); else cp_wait<0>();
        __syncthreads();
        if (t + 2 < T) prefetch(t + 2, (t + 2) % STAGES);

        const int s = t % STAGES;
        const uint32_t* Ab = (const uint32_t*)(As + s * AS_FLOATS);
        const uint32_t* Bb = (const uint32_t*)(Bs + s * AS_FLOATS);
#pragma unroll
        for (int kk = 0; kk < 2; ++kk) {
            uint32_t a[4][4];
#pragma unroll
            for (int mi = 0; mi < 4; ++mi) {
                const uint32_t* p = Ab + (wm * 64 + mi * 16 + g) * AS_STRIDE + kk * 8 + tig;
                a[mi][0] = p[0];
                a[mi][2] = p[4];
                a[mi][1] = p[8 * AS_STRIDE];
                a[mi][3] = p[8 * AS_STRIDE + 4];
            }
#pragma unroll
            for (int ni = 0; ni < 4; ++ni) {
                const uint32_t* q = Bb + (wn * 32 + ni * 8 + g) * AS_STRIDE + kk * 8 + tig;
                uint32_t bf0 = q[0], bf1 = q[4];
#pragma unroll
                for (int mi = 0; mi < 4; ++mi) mma8(acc[mi][ni], a[mi], bf0, bf1);
            }
        }
    }

    // epilogue: +bias, round to tf32 (consumers do raw-bit MMA)
#pragma unroll
    for (int mi = 0; mi < 4; ++mi) {
        const int row = m0 + wm * 64 + mi * 16 + g;
#pragma unroll
        for (int ni = 0; ni < 4; ++ni) {
            const int col = n0 + wn * 32 + ni * 8 + 2 * tig;
            const float b0v = bias[col], b1v = bias[col + 1];
            float2 r0 = {f2tff(acc[mi][ni][0] + b0v), f2tff(acc[mi][ni][1] + b1v)};
            float2 r1 = {f2tff(acc[mi][ni][2] + b0v), f2tff(acc[mi][ni][3] + b1v)};
            *(float2*)(out + (size_t)row * EMB + col)       = r0;
            *(float2*)(out + (size_t)(row + 8) * EMB + col) = r1;
        }
    }
}

// ---------------------------------------------------------------------------
// Kernel 2: scores. P[b][q][n] = (Q[b][q].K[b][n]) / 32  (fp32 output)
// Only lower-triangular tiles.
// ---------------------------------------------------------------------------
__global__ void __launch_bounds__(NTHREADS, 2)
scores_kernel()
{
    const int qt = blockIdx.y, nt = blockIdx.x;
    if (nt > qt) return;
    const int b = blockIdx.z;

    extern __shared__ float smem[];
    float* As = smem;
    float* Bs = smem + STAGES * AS_FLOATS;

    const float* Q  = g_qkv[0] + (size_t)b * SEQ * EMB;
    const float* Km = g_qkv[1] + (size_t)b * SEQ * EMB;
    float* P = g_p + (size_t)b * SEQ * SEQ;

    const int m0 = qt * BM, n0 = nt * BN;
    const int tid = threadIdx.x;
    const int warp = tid >> 5, lane = tid & 31;
    const int wm = warp & 1, wn = warp >> 1;
    const int g = lane >> 2, tig = lane & 3;

    const int ar = tid >> 2, ac = (tid & 3) * 4;
    const float* ag = Q  + (size_t)(m0 + ar) * EMB + ac;
    const float* bg = Km + (size_t)(n0 + ar) * EMB + ac;
    const uint32_t asw = (uint32_t)__cvta_generic_to_shared(As) + (ar * AS_STRIDE + ac) * 4;
    const uint32_t bsw = (uint32_t)__cvta_generic_to_shared(Bs) + (ar * AS_STRIDE + ac) * 4;
    const uint32_t BUF = AS_FLOATS * 4;
    const uint32_t ROWS64 = 64 * AS_STRIDE * 4;

    float acc[4][4][4];
#pragma unroll
    for (int i = 0; i < 4; i++)
#pragma unroll
        for (int j = 0; j < 4; j++)
#pragma unroll
            for (int k = 0; k < 4; k++) acc[i][j][k] = 0.f;

    auto prefetch = [&](int t, int s) {
        const float* a2 = ag + t * BK;
        const float* b2 = bg + t * BK;
        const uint32_t off = s * BUF;
        cp16(asw + off, a2);  cp16(asw + off + ROWS64, a2 + (size_t)64 * EMB);
        cp16(bsw + off, b2);  cp16(bsw + off + ROWS64, b2 + (size_t)64 * EMB);
        cp_commit();
    };

    const int T = EMB / BK;
    prefetch(0, 0);
    prefetch(1, 1);

    for (int t = 0; t < T; ++t) {
        if (t + 1 < T) cp_wait<1>(); else cp_wait<0>();
        __syncthreads();
        if (t + 2 < T) prefetch(t + 2, (t + 2) % STAGES);

        const int s = t % STAGES;
        const uint32_t* Ab = (const uint32_t*)(As + s * AS_FLOATS);
        const uint32_t* Bb = (const uint32_t*)(Bs + s * AS_FLOATS);
#pragma unroll
        for (int kk = 0; kk < 2; ++kk) {
            uint32_t a[4][4];
#pragma unroll
            for (int mi = 0; mi < 4; ++mi) {
                const uint32_t* p = Ab + (wm * 64 + mi * 16 + g) * AS_STRIDE + kk * 8 + tig;
                a[mi][0] = p[0];
                a[mi][2] = p[4];
                a[mi][1] = p[8 * AS_STRIDE];
                a[mi][3] = p[8 * AS_STRIDE + 4];
            }
#pragma unroll
            for (int ni = 0; ni < 4; ++ni) {
                const uint32_t* q = Bb + (wn * 32 + ni * 8 + g) * AS_STRIDE + kk * 8 + tig;
                uint32_t bf0 = q[0], bf1 = q[4];
#pragma unroll
                for (int mi = 0; mi < 4; ++mi) mma8(acc[mi][ni], a[mi], bf0, bf1);
            }
        }
    }

    const float scale = 0.03125f;  // 1/sqrt(1024)
#pragma unroll
    for (int mi = 0; mi < 4; ++mi) {
        const int row = m0 + wm * 64 + mi * 16 + g;
#pragma unroll
        for (int ni = 0; ni < 4; ++ni) {
            const int col = n0 + wn * 32 + ni * 8 + 2 * tig;
            float2 r0 = {acc[mi][ni][0] * scale, acc[mi][ni][1] * scale};
            float2 r1 = {acc[mi][ni][2] * scale, acc[mi][ni][3] * scale};
            *(float2*)(P + (size_t)row * SEQ + col)       = r0;
            *(float2*)(P + (size_t)(row + 8) * SEQ + col) = r1;
        }
    }
}

// ---------------------------------------------------------------------------
// Kernel 3: row softmax over [0..q]; tf32-rounded probs; zeros only up to the
// enclosing 128-tile boundary (pv never reads beyond it).
// ---------------------------------------------------------------------------
__global__ void __launch_bounds__(NTHREADS)
softmax_kernel()
{
    __shared__ float buf[SEQ];
    __shared__ float red[8];

    const int q = blockIdx.x & (SEQ - 1);
    const int b = blockIdx.x >> 11;
    float* row = g_p + ((size_t)b * SEQ + q) * SEQ;
    const int n = q + 1;
    const int zend = ((q >> 7) + 1) << 7;   // tile-aligned end of pv's K extent
    const int tid = threadIdx.x;
    const int lane = tid & 31;
    const int wid = tid >> 5;

    float lmax = -1e30f;
    for (int i = tid; i < n; i += NTHREADS) {
        float v = row[i];
        buf[i] = v;
        lmax = fmaxf(lmax, v);
    }
#pragma unroll
    for (int off = 16; off; off >>= 1)
        lmax = fmaxf(lmax, __shfl_xor_sync(0xffffffffu, lmax, off));
    if (lane == 0) red[wid] = lmax;
    __syncthreads();
    float gmax = red[0];
#pragma unroll
    for (int w = 1; w < 8; w++) gmax = fmaxf(gmax, red[w]);
    __syncthreads();

    float lsum = 0.f;
    for (int i = tid; i < n; i += NTHREADS) {
        float e = __expf(buf[i] - gmax);
        buf[i] = e;
        lsum += e;
    }
#pragma unroll
    for (int off = 16; off; off >>= 1)
        lsum += __shfl_xor_sync(0xffffffffu, lsum, off);
    if (lane == 0) red[wid] = lsum;
    __syncthreads();
    float gsum = red[0];
#pragma unroll
    for (int w = 1; w < 8; w++) gsum += red[w];

    const float inv = 1.f / gsum;
    for (int i = tid; i < n; i += NTHREADS) row[i] = f2tff(buf[i] * inv);
    for (int i = n + tid; i < zend; i += NTHREADS) row[i] = 0.f;
}

// ---------------------------------------------------------------------------
// Kernel 4: O = P @ V (NN GEMM, causal-truncated K extent).
// Dynamic smem: STAGES * (As + Vs) = 3 * (2560 + 2176) floats = 56832 B
// ---------------------------------------------------------------------------
__global__ void __launch_bounds__(NTHREADS, 2)
pv_kernel(float* __restrict__ out)
{
    extern __shared__ float smem[];
    float* As = smem;                       // [STAGES][AS_FLOATS]
    float* Vs = smem + STAGES * AS_FLOATS;  // [STAGES][VS_FLOATS]

    const int b  = blockIdx.z;
    const int mt = blockIdx.y;
    const int e0 = blockIdx.x * BN;

    const float* P = g_p + (size_t)b * SEQ * SEQ;
    const float* V = g_qkv[2] + (size_t)b * SEQ * EMB;

    const int m0 = mt * BM;
    const int tid = threadIdx.x;
    const int warp = tid >> 5, lane = tid & 31;
    const int wm = warp & 1, wn = warp >> 1;
    const int g = lane >> 2, tig = lane & 3;

    const int ar = tid >> 2, ac = (tid & 3) * 4;
    const float* ag = P + (size_t)(m0 + ar) * SEQ + ac;
    const uint32_t asw = (uint32_t)__cvta_generic_to_shared(As) + (ar * AS_STRIDE + ac) * 4;
    const int vk = tid >> 5, vn = (tid & 31) * 4;
    const float* vg = V + (size_t)vk * EMB + e0 + vn;
    const uint32_t vsw = (uint32_t)__cvta_generic_to_shared(Vs) + (vk * VS_STRIDE + vn) * 4;
    const uint32_t ABUF = AS_FLOATS * 4;
    const uint32_t VBUF = VS_FLOATS * 4;
    const uint32_t AROWS64 = 64 * AS_STRIDE * 4;
    const uint32_t VROWS8  = 8 * VS_STRIDE * 4;

    float acc[4][4][4];
#pragma unroll
    for (int i = 0; i < 4; i++)
#pragma unroll
        for (int j = 0; j < 4; j++)
#pragma unroll
            for (int k = 0; k < 4; k++) acc[i][j][k] = 0.f;

    auto prefetch = [&](int t, int s) {
        const float* a2 = ag + t * BK;
        const float* v2 = vg + (size_t)t * BK * EMB;
        cp16(asw + s * ABUF, a2);  cp16(asw + s * ABUF + AROWS64, a2 + (size_t)64 * SEQ);
        cp16(vsw + s * VBUF, v2);  cp16(vsw + s * VBUF + VROWS8,  v2 + (size_t)8 * EMB);
        cp_commit();
    };

    const int T = (mt + 1) * (BM / BK);
    prefetch(0, 0);
    prefetch(1, 1);

    for (int t = 0; t < T; ++t) {
        if (t + 1 < T) cp_wait<1>(); else cp_wait<0>();
        __syncthreads();
        if (t + 2 < T) prefetch(t + 2, (t + 2) % STAGES);

        const int s = t % STAGES;
        const uint32_t* Ab = (const uint32_t*)(As + s * AS_FLOATS);
        const uint32_t* Vb = (const uint32_t*)(Vs + s * VS_FLOATS);
#pragma unroll
        for (int kk = 0; kk < 2; ++kk) {
            uint32_t a[4][4];
#pragma unroll
            for (int mi = 0; mi < 4; ++mi) {
                const uint32_t* p = Ab + (wm * 64 + mi * 16 + g) * AS_STRIDE + kk * 8 + tig;
                a[mi][0] = p[0];
                a[mi][2] = p[4];
                a[mi][1] = p[8 * AS_STRIDE];
                a[mi][3] = p[8 * AS_STRIDE + 4];
            }
#pragma unroll
            for (int ni = 0; ni < 4; ++ni) {
                const uint32_t* q = Vb + (kk * 8 + tig) * VS_STRIDE + wn * 32 + ni * 8 + g;
                uint32_t bf0 = q[0], bf1 = q[4 * VS_STRIDE];
#pragma unroll
                for (int mi = 0; mi < 4; ++mi) mma8(acc[mi][ni], a[mi], bf0, bf1);
            }
        }
    }

#pragma unroll
    for (int mi = 0; mi < 4; ++mi) {
        const int row = m0 + wm * 64 + mi * 16 + g;
#pragma unroll
        for (int ni = 0; ni < 4; ++ni) {
            const int col = e0 + wn * 32 + ni * 8 + 2 * tig;
            float2 r0 = {acc[mi][ni][0], acc[mi][ni][1]};
            float2 r1 = {acc[mi][ni][2], acc[mi][ni][3]};
            *(float2*)(out + ((size_t)b * SEQ + row) * EMB + col)     = r0;
            *(float2*)(out + ((size_t)b * SEQ + row + 8) * EMB + col) = r1;
        }
    }
}

// ---------------------------------------------------------------------------
extern "C" void kernel_launch(void* const* d_in, const int* in_sizes, int n_in,
                              void* d_out, int out_size)
{
    const float* xs = (const float*)d_in[0];
    const float* wq = (const float*)d_in[1];
    const float* bq = (const float*)d_in[2];
    const float* wk = (const float*)d_in[3];
    const float* bk = (const float*)d_in[4];
    const float* wv = (const float*)d_in[5];
    const float* bv = (const float*)d_in[6];
    float* out = (float*)d_out;

    const int QKV_SMEM = STAGES * 2 * AS_FLOATS * 4;              // 61440 B
    const int PV_SMEM  = STAGES * (AS_FLOATS + VS_FLOATS) * 4;    // 56832 B
    cudaFuncSetAttribute(qkv_kernel,    cudaFuncAttributeMaxDynamicSharedMemorySize, QKV_SMEM);
    cudaFuncSetAttribute(scores_kernel, cudaFuncAttributeMaxDynamicSharedMemorySize, QKV_SMEM);
    cudaFuncSetAttribute(pv_kernel,     cudaFuncAttributeMaxDynamicSharedMemorySize, PV_SMEM);

    // 0: tf32-round x and weights into scratch
    const int xn4 = (BATCH * SEQ * HDIM) / 4;     // 2,097,152
    const int wn4 = (EMB * HDIM) / 4;             // 262,144
    cvt_kernel<<<(xn4 + NTHREADS - 1) / NTHREADS, NTHREADS>>>((const float4*)xs, 0, xn4);
    cvt_kernel<<<(wn4 + NTHREADS - 1) / NTHREADS, NTHREADS>>>((const float4*)wq, 1, wn4);
    cvt_kernel<<<(wn4 + NTHREADS - 1) / NTHREADS, NTHREADS>>>((const float4*)wk, 2, wn4);
    cvt_kernel<<<(wn4 + NTHREADS - 1) / NTHREADS, NTHREADS>>>((const float4*)wv, 3, wn4);

    dim3 gqkv(EMB / BN, (BATCH * SEQ) / BM, 3);          // (8, 64, 3)
    qkv_kernel<<<gqkv, NTHREADS, QKV_SMEM>>>(bq, bk, bv);

    dim3 gsc(SEQ / BN, SEQ / BM, BATCH);                 // (16, 16, 4)
    scores_kernel<<<gsc, NTHREADS, QKV_SMEM>>>();

    softmax_kernel<<<BATCH * SEQ, NTHREADS>>>();         // 8192 blocks

    dim3 gpv(EMB / BN, SEQ / BM, BATCH);                 // (8, 16, 4)
    pv_kernel<<<gpv, NTHREADS, PV_SMEM>>>(out);
}

// round 8
// speedup vs baseline: 1.6858x; 1.6858x over previous
#include <cuda_runtime.h>
#include <cuda_fp16.h>
#include <cstdint>

// Problem constants
#define BATCH 4
#define SEQ   2048
#define EMB   1024
#define HDIM  1024
#define NTHREADS 256

// fp16 GEMM tiling: 128x128 CTA tile, K-chunk 32 halves, 4-stage cp.async ring
#define HCHUNK  32
#define HSTAGES 4
#define HROWB   80                    // smem bytes per 32-half row (64 + 16 pad)
#define HTILEB  (128 * HROWB)         // 10240 B per operand stage
#define VROWB   272                   // V tile: 128 halves + 8 pad = 272 B/row
#define VTILEB  (HCHUNK * VROWB)      // 8704 B per V stage

// Scratch (static device allocations)
__device__ __half g_xh[(size_t)BATCH * SEQ * HDIM];      // fp16 x
__device__ __half g_wh[3][(size_t)EMB * HDIM];           // fp16 weights
__device__ __half g_qkvh[3][(size_t)BATCH * SEQ * EMB];  // fp16 Q,K,V
__device__ float  g_p[(size_t)BATCH * SEQ * SEQ];        // fp32 scores
__device__ __half g_ph[(size_t)BATCH * SEQ * SEQ];       // fp16 probs

// ---------------------------------------------------------------------------
// PTX helpers
// ---------------------------------------------------------------------------
__device__ __forceinline__ void cp16(uint32_t dst, const void* src) {
    asm volatile("cp.async.ca.shared.global [%0], [%1], 16;" :: "r"(dst), "l"(src));
}
__device__ __forceinline__ void cp_commit() { asm volatile("cp.async.commit_group;"); }
template <int N>
__device__ __forceinline__ void cp_wait() { asm volatile("cp.async.wait_group %0;" :: "n"(N)); }

__device__ __forceinline__ void ldsm4(uint32_t* r, uint32_t addr) {
    asm volatile("ldmatrix.sync.aligned.m8n8.x4.shared.b16 {%0,%1,%2,%3}, [%4];"
                 : "=r"(r[0]), "=r"(r[1]), "=r"(r[2]), "=r"(r[3]) : "r"(addr));
}
__device__ __forceinline__ void ldsm4t(uint32_t* r, uint32_t addr) {
    asm volatile("ldmatrix.sync.aligned.m8n8.x4.trans.shared.b16 {%0,%1,%2,%3}, [%4];"
                 : "=r"(r[0]), "=r"(r[1]), "=r"(r[2]), "=r"(r[3]) : "r"(addr));
}
__device__ __forceinline__ void mma16(float* c, const uint32_t* a, const uint32_t* b) {
    asm volatile(
        "mma.sync.aligned.m16n8k16.row.col.f32.f16.f16.f32 "
        "{%0,%1,%2,%3}, {%4,%5,%6,%7}, {%8,%9}, {%0,%1,%2,%3};"
        : "+f"(c[0]), "+f"(c[1]), "+f"(c[2]), "+f"(c[3])
        : "r"(a[0]), "r"(a[1]), "r"(a[2]), "r"(a[3]), "r"(b[0]), "r"(b[1]));
}

// ---------------------------------------------------------------------------
// Kernel 0: fp32 -> fp16 conversion of x / W.
// which: 0 -> g_xh, 1..3 -> g_wh[which-1]
// ---------------------------------------------------------------------------
__global__ void __launch_bounds__(NTHREADS)
cvt_kernel(const float4* __restrict__ src, int which, int n4)
{
    __half* dstf = (which == 0) ? g_xh : g_wh[which - 1];
    int i = blockIdx.x * NTHREADS + threadIdx.x;
    if (i < n4) {
        float4 v = src[i];
        __half2 h0 = __floats2half2_rn(v.x, v.y);
        __half2 h1 = __floats2half2_rn(v.z, v.w);
        uint2 u;
        u.x = *reinterpret_cast<uint32_t*>(&h0);
        u.y = *reinterpret_cast<uint32_t*>(&h1);
        ((uint2*)dstf)[i] = u;
    }
}

// ---------------------------------------------------------------------------
// Kernel 1: QKV projection, NT fp16 GEMM + bias. grid (8, 64, 3).
// ---------------------------------------------------------------------------
__global__ void __launch_bounds__(NTHREADS, 2)
qkv_kernel(const float* __restrict__ bi0,
           const float* __restrict__ bi1,
           const float* __restrict__ bi2)
{
    extern __shared__ char dsm[];
    const uint32_t Abase = (uint32_t)__cvta_generic_to_shared(dsm);
    const uint32_t Bbase = Abase + HSTAGES * HTILEB;

    const int which = blockIdx.z;
    const __half* Ag = g_xh;
    const __half* Bg = g_wh[which];
    const float* bias = (which == 0) ? bi0 : (which == 1) ? bi1 : bi2;
    __half* out = g_qkvh[which];

    const int m0 = blockIdx.y * 128, n0 = blockIdx.x * 128;
    const int tid = threadIdx.x;
    const int warp = tid >> 5, lane = tid & 31;
    const int wm = warp & 1, wn = warp >> 1;
    const int g = lane >> 2, tig = lane & 3;

    // cp.async loader mapping: row = tid>>1 (0..127), chunks (tid&1), (tid&1)+2
    const int lr = tid >> 1, lc0 = tid & 1;
    const __half* agp = Ag + (size_t)(m0 + lr) * HDIM;
    const __half* bgp = Bg + (size_t)(n0 + lr) * HDIM;
    const uint32_t asw = Abase + lr * HROWB;
    const uint32_t bsw = Bbase + lr * HROWB;

    // ldmatrix per-lane offsets
    const uint32_t aoff = ((lane & 7) + ((lane >> 3) & 1) * 8) * HROWB + (lane >> 4) * 16;
    const uint32_t boff = (((lane >> 4) << 3) + (lane & 7)) * HROWB + ((lane >> 3) & 1) * 16;

    float acc[4][4][4];
#pragma unroll
    for (int i = 0; i < 4; i++)
#pragma unroll
        for (int j = 0; j < 4; j++)
#pragma unroll
            for (int k = 0; k < 4; k++) acc[i][j][k] = 0.f;

    auto pre = [&](int c, int s) {
        const __half* ap = agp + c * HCHUNK;
        const __half* bp = bgp + c * HCHUNK;
        const uint32_t as = asw + s * HTILEB;
        const uint32_t bs = bsw + s * HTILEB;
        cp16(as + lc0 * 16,       ap + lc0 * 8);
        cp16(as + (lc0 + 2) * 16, ap + (lc0 + 2) * 8);
        cp16(bs + lc0 * 16,       bp + lc0 * 8);
        cp16(bs + (lc0 + 2) * 16, bp + (lc0 + 2) * 8);
        cp_commit();
    };

    const int T = HDIM / HCHUNK;   // 32
    pre(0, 0); pre(1, 1); pre(2, 2);

    for (int t = 0; t < T; ++t) {
        if (t + 2 < T) cp_wait<2>(); else if (t + 1 < T) cp_wait<1>(); else cp_wait<0>();
        __syncthreads();
        if (t + 3 < T) pre(t + 3, (t + 3) & 3);

        const int s = t & 3;
        const uint32_t Ab = Abase + s * HTILEB;
        const uint32_t Bb = Bbase + s * HTILEB;
#pragma unroll
        for (int kk = 0; kk < 2; ++kk) {
            uint32_t a[4][4];
#pragma unroll
            for (int mi = 0; mi < 4; ++mi)
                ldsm4(a[mi], Ab + (wm * 64 + mi * 16) * HROWB + kk * 32 + aoff);
            uint32_t b[2][4];
#pragma unroll
            for (int p = 0; p < 2; ++p)
                ldsm4(b[p], Bb + (wn * 32 + p * 16) * HROWB + kk * 32 + boff);
#pragma unroll
            for (int mi = 0; mi < 4; ++mi)
#pragma unroll
                for (int ni = 0; ni < 4; ++ni)
                    mma16(acc[mi][ni], a[mi], &b[ni >> 1][(ni & 1) * 2]);
        }
    }

    // epilogue: +bias, round to fp16, store
#pragma unroll
    for (int mi = 0; mi < 4; ++mi) {
        const int row = m0 + wm * 64 + mi * 16 + g;
#pragma unroll
        for (int ni = 0; ni < 4; ++ni) {
            const int col = n0 + wn * 32 + ni * 8 + 2 * tig;
            const float b0v = bias[col], b1v = bias[col + 1];
            __half2 h0 = __floats2half2_rn(acc[mi][ni][0] + b0v, acc[mi][ni][1] + b1v);
            __half2 h1 = __floats2half2_rn(acc[mi][ni][2] + b0v, acc[mi][ni][3] + b1v);
            *(__half2*)(out + (size_t)row * EMB + col)       = h0;
            *(__half2*)(out + (size_t)(row + 8) * EMB + col) = h1;
        }
    }
}

// ---------------------------------------------------------------------------
// Kernel 2: scores, NT fp16 GEMM, lower-tri tiles only, fp32 out.
// ---------------------------------------------------------------------------
__global__ void __launch_bounds__(NTHREADS, 2)
scores_kernel()
{
    const int qt = blockIdx.y, nt = blockIdx.x;
    if (nt > qt) return;
    const int b = blockIdx.z;

    extern __shared__ char dsm[];
    const uint32_t Abase = (uint32_t)__cvta_generic_to_shared(dsm);
    const uint32_t Bbase = Abase + HSTAGES * HTILEB;

    const __half* Q  = g_qkvh[0] + (size_t)b * SEQ * EMB;
    const __half* Km = g_qkvh[1] + (size_t)b * SEQ * EMB;
    float* P = g_p + (size_t)b * SEQ * SEQ;

    const int m0 = qt * 128, n0 = nt * 128;
    const int tid = threadIdx.x;
    const int warp = tid >> 5, lane = tid & 31;
    const int wm = warp & 1, wn = warp >> 1;
    const int g = lane >> 2, tig = lane & 3;

    const int lr = tid >> 1, lc0 = tid & 1;
    const __half* agp = Q  + (size_t)(m0 + lr) * EMB;
    const __half* bgp = Km + (size_t)(n0 + lr) * EMB;
    const uint32_t asw = Abase + lr * HROWB;
    const uint32_t bsw = Bbase + lr * HROWB;

    const uint32_t aoff = ((lane & 7) + ((lane >> 3) & 1) * 8) * HROWB + (lane >> 4) * 16;
    const uint32_t boff = (((lane >> 4) << 3) + (lane & 7)) * HROWB + ((lane >> 3) & 1) * 16;

    float acc[4][4][4];
#pragma unroll
    for (int i = 0; i < 4; i++)
#pragma unroll
        for (int j = 0; j < 4; j++)
#pragma unroll
            for (int k = 0; k < 4; k++) acc[i][j][k] = 0.f;

    auto pre = [&](int c, int s) {
        const __half* ap = agp + c * HCHUNK;
        const __half* bp = bgp + c * HCHUNK;
        const uint32_t as = asw + s * HTILEB;
        const uint32_t bs = bsw + s * HTILEB;
        cp16(as + lc0 * 16,       ap + lc0 * 8);
        cp16(as + (lc0 + 2) * 16, ap + (lc0 + 2) * 8);
        cp16(bs + lc0 * 16,       bp + lc0 * 8);
        cp16(bs + (lc0 + 2) * 16, bp + (lc0 + 2) * 8);
        cp_commit();
    };

    const int T = EMB / HCHUNK;
    pre(0, 0); pre(1, 1); pre(2, 2);

    for (int t = 0; t < T; ++t) {
        if (t + 2 < T) cp_wait<2>(); else if (t + 1 < T) cp_wait<1>(); else cp_wait<0>();
        __syncthreads();
        if (t + 3 < T) pre(t + 3, (t + 3) & 3);

        const int s = t & 3;
        const uint32_t Ab = Abase + s * HTILEB;
        const uint32_t Bb = Bbase + s * HTILEB;
#pragma unroll
        for (int kk = 0; kk < 2; ++kk) {
            uint32_t a[4][4];
#pragma unroll
            for (int mi = 0; mi < 4; ++mi)
                ldsm4(a[mi], Ab + (wm * 64 + mi * 16) * HROWB + kk * 32 + aoff);
            uint32_t b[2][4];
#pragma unroll
            for (int p = 0; p < 2; ++p)
                ldsm4(b[p], Bb + (wn * 32 + p * 16) * HROWB + kk * 32 + boff);
#pragma unroll
            for (int mi = 0; mi < 4; ++mi)
#pragma unroll
                for (int ni = 0; ni < 4; ++ni)
                    mma16(acc[mi][ni], a[mi], &b[ni >> 1][(ni & 1) * 2]);
        }
    }

    const float scale = 0.03125f;  // 1/sqrt(1024)
#pragma unroll
    for (int mi = 0; mi < 4; ++mi) {
        const int row = m0 + wm * 64 + mi * 16 + g;
#pragma unroll
        for (int ni = 0; ni < 4; ++ni) {
            const int col = n0 + wn * 32 + ni * 8 + 2 * tig;
            float2 r0 = {acc[mi][ni][0] * scale, acc[mi][ni][1] * scale};
            float2 r1 = {acc[mi][ni][2] * scale, acc[mi][ni][3] * scale};
            *(float2*)(P + (size_t)row * SEQ + col)       = r0;
            *(float2*)(P + (size_t)(row + 8) * SEQ + col) = r1;
        }
    }
}

// ---------------------------------------------------------------------------
// Kernel 3: row softmax over [0..q]; fp16 probs out; zero-fill to tile end.
// ---------------------------------------------------------------------------
__global__ void __launch_bounds__(NTHREADS)
softmax_kernel()
{
    __shared__ float buf[SEQ];
    __shared__ float red[8];

    const int q = blockIdx.x & (SEQ - 1);
    const int b = blockIdx.x >> 11;
    const float* row = g_p + ((size_t)b * SEQ + q) * SEQ;
    __half* orow = g_ph + ((size_t)b * SEQ + q) * SEQ;
    const int n = q + 1;
    const int zend = ((q >> 7) + 1) << 7;
    const int tid = threadIdx.x;
    const int lane = tid & 31;
    const int wid = tid >> 5;

    float lmax = -1e30f;
    for (int i = tid; i < n; i += NTHREADS) {
        float v = row[i];
        buf[i] = v;
        lmax = fmaxf(lmax, v);
    }
#pragma unroll
    for (int off = 16; off; off >>= 1)
        lmax = fmaxf(lmax, __shfl_xor_sync(0xffffffffu, lmax, off));
    if (lane == 0) red[wid] = lmax;
    __syncthreads();
    float gmax = red[0];
#pragma unroll
    for (int w = 1; w < 8; w++) gmax = fmaxf(gmax, red[w]);
    __syncthreads();

    float lsum = 0.f;
    for (int i = tid; i < n; i += NTHREADS) {
        float e = __expf(buf[i] - gmax);
        buf[i] = e;
        lsum += e;
    }
#pragma unroll
    for (int off = 16; off; off >>= 1)
        lsum += __shfl_xor_sync(0xffffffffu, lsum, off);
    if (lane == 0) red[wid] = lsum;
    __syncthreads();
    float gsum = red[0];
#pragma unroll
    for (int w = 1; w < 8; w++) gsum += red[w];

    const float inv = 1.f / gsum;
    for (int i = tid; i < n; i += NTHREADS) orow[i] = __float2half_rn(buf[i] * inv);
    const __half hz = __float2half_rn(0.f);
    for (int i = n + tid; i < zend; i += NTHREADS) orow[i] = hz;
}

// ---------------------------------------------------------------------------
// Kernel 4: O = P @ V, NN fp16 GEMM (V loaded with ldmatrix.trans),
// causal-truncated K extent. fp32 out.
// ---------------------------------------------------------------------------
__global__ void __launch_bounds__(NTHREADS, 2)
pv_kernel(float* __restrict__ out)
{
    extern __shared__ char dsm[];
    const uint32_t Abase = (uint32_t)__cvta_generic_to_shared(dsm);
    const uint32_t Vbase = Abase + HSTAGES * HTILEB;

    const int b  = blockIdx.z;
    const int mt = blockIdx.y;
    const int e0 = blockIdx.x * 128;

    const __half* P = g_ph + (size_t)b * SEQ * SEQ;
    const __half* V = g_qkvh[2] + (size_t)b * SEQ * EMB;

    const int m0 = mt * 128;
    const int tid = threadIdx.x;
    const int warp = tid >> 5, lane = tid & 31;
    const int wm = warp & 1, wn = warp >> 1;
    const int g = lane >> 2, tig = lane & 3;

    // A (P) loader: row = tid>>1, chunks (tid&1), (tid&1)+2
    const int lr = tid >> 1, lc0 = tid & 1;
    const __half* agp = P + (size_t)(m0 + lr) * SEQ;
    const uint32_t asw = Abase + lr * HROWB;
    // V loader: k-row = tid>>3 (0..31), chunks (tid&7), (tid&7)+8
    const int vr = tid >> 3, vc = tid & 7;
    const __half* vgp = V + (size_t)vr * EMB + e0;
    const uint32_t vsw = Vbase + vr * VROWB;

    const uint32_t aoff = ((lane & 7) + ((lane >> 3) & 1) * 8) * HROWB + (lane >> 4) * 16;
    const uint32_t voff = ((lane & 7) + ((lane >> 3) & 1) * 8) * VROWB + (lane >> 4) * 16;

    float acc[4][4][4];
#pragma unroll
    for (int i = 0; i < 4; i++)
#pragma unroll
        for (int j = 0; j < 4; j++)
#pragma unroll
            for (int k = 0; k < 4; k++) acc[i][j][k] = 0.f;

    auto pre = [&](int c, int s) {
        const __half* ap = agp + c * HCHUNK;
        const __half* vp = vgp + (size_t)c * HCHUNK * EMB;
        const uint32_t as = asw + s * HTILEB;
        const uint32_t vs = vsw + s * VTILEB;
        cp16(as + lc0 * 16,       ap + lc0 * 8);
        cp16(as + (lc0 + 2) * 16, ap + (lc0 + 2) * 8);
        cp16(vs + vc * 16,        vp + vc * 8);
        cp16(vs + (vc + 8) * 16,  vp + (vc + 8) * 8);
        cp_commit();
    };

    const int T = (mt + 1) * 4;   // (mt+1)*128 / 32
    pre(0, 0); pre(1, 1); pre(2, 2);

    for (int t = 0; t < T; ++t) {
        if (t + 2 < T) cp_wait<2>(); else if (t + 1 < T) cp_wait<1>(); else cp_wait<0>();
        __syncthreads();
        if (t + 3 < T) pre(t + 3, (t + 3) & 3);

        const int s = t & 3;
        const uint32_t Ab = Abase + s * HTILEB;
        const uint32_t Vb = Vbase + s * VTILEB;
#pragma unroll
        for (int kk = 0; kk < 2; ++kk) {
            uint32_t a[4][4];
#pragma unroll
            for (int mi = 0; mi < 4; ++mi)
                ldsm4(a[mi], Ab + (wm * 64 + mi * 16) * HROWB + kk * 32 + aoff);
            uint32_t b2[2][4];
#pragma unroll
            for (int p = 0; p < 2; ++p)
                ldsm4t(b2[p], Vb + kk * 16 * VROWB + (wn * 32 + p * 16) * 2 + voff);
#pragma unroll
            for (int mi = 0; mi < 4; ++mi)
#pragma unroll
                for (int ni = 0; ni < 4; ++ni)
                    mma16(acc[mi][ni], a[mi], &b2[ni >> 1][(ni & 1) * 2]);
        }
    }

#pragma unroll
    for (int mi = 0; mi < 4; ++mi) {
        const int row = m0 + wm * 64 + mi * 16 + g;
#pragma unroll
        for (int ni = 0; ni < 4; ++ni) {
            const int col = e0 + wn * 32 + ni * 8 + 2 * tig;
            float2 r0 = {acc[mi][ni][0], acc[mi][ni][1]};
            float2 r1 = {acc[mi][ni][2], acc[mi][ni][3]};
            *(float2*)(out + ((size_t)b * SEQ + row) * EMB + col)     = r0;
            *(float2*)(out + ((size_t)b * SEQ + row + 8) * EMB + col) = r1;
        }
    }
}

// ---------------------------------------------------------------------------
extern "C" void kernel_launch(void* const* d_in, const int* in_sizes, int n_in,
                              void* d_out, int out_size)
{
    const float* xs = (const float*)d_in[0];
    const float* wq = (const float*)d_in[1];
    const float* bq = (const float*)d_in[2];
    const float* wk = (const float*)d_in[3];
    const float* bk = (const float*)d_in[4];
    const float* wv = (const float*)d_in[5];
    const float* bv = (const float*)d_in[6];
    float* out = (float*)d_out;

    const int QS_SMEM = HSTAGES * 2 * HTILEB;             // 81920 B
    const int PV_SMEM = HSTAGES * (HTILEB + VTILEB);      // 75776 B
    cudaFuncSetAttribute(qkv_kernel,    cudaFuncAttributeMaxDynamicSharedMemorySize, QS_SMEM);
    cudaFuncSetAttribute(scores_kernel, cudaFuncAttributeMaxDynamicSharedMemorySize, QS_SMEM);
    cudaFuncSetAttribute(pv_kernel,     cudaFuncAttributeMaxDynamicSharedMemorySize, PV_SMEM);

    // 0: fp16-convert x and weights
    const int xn4 = (BATCH * SEQ * HDIM) / 4;
    const int wn4 = (EMB * HDIM) / 4;
    cvt_kernel<<<(xn4 + NTHREADS - 1) / NTHREADS, NTHREADS>>>((const float4*)xs, 0, xn4);
    cvt_kernel<<<(wn4 + NTHREADS - 1) / NTHREADS, NTHREADS>>>((const float4*)wq, 1, wn4);
    cvt_kernel<<<(wn4 + NTHREADS - 1) / NTHREADS, NTHREADS>>>((const float4*)wk, 2, wn4);
    cvt_kernel<<<(wn4 + NTHREADS - 1) / NTHREADS, NTHREADS>>>((const float4*)wv, 3, wn4);

    dim3 gqkv(EMB / 128, (BATCH * SEQ) / 128, 3);        // (8, 64, 3)
    qkv_kernel<<<gqkv, NTHREADS, QS_SMEM>>>(bq, bk, bv);

    dim3 gsc(SEQ / 128, SEQ / 128, BATCH);               // (16, 16, 4)
    scores_kernel<<<gsc, NTHREADS, QS_SMEM>>>();

    softmax_kernel<<<BATCH * SEQ, NTHREADS>>>();         // 8192 blocks

    dim3 gpv(EMB / 128, SEQ / 128, BATCH);               // (8, 16, 4)
    pv_kernel<<<gpv, NTHREADS, PV_SMEM>>>(out);
}

// round 9
// speedup vs baseline: 1.6968x; 1.0065x over previous
#include <cuda_runtime.h>
#include <cuda_fp16.h>
#include <cstdint>

// Problem constants
#define BATCH 4
#define SEQ   2048
#define EMB   1024
#define HDIM  1024
#define NTHREADS 256

// GEMM tiling: CTA 128(M) x 256(N), warp tile 64x64, K-chunk 64, 4-stage ring
#define KC      64                    // K halves per chunk (128 B per row)
#define NSTG    4
#define ATILEB  (128 * 128)           // 16384 B : 128 rows x 128 B
#define BTILEB  (256 * 128)           // 32768 B : 256 rows x 128 B
#define VTILEB  (64 * 512)            // 32768 B : 64 k-rows x 512 B (256 e-cols)

// Scratch (static device allocations)
__device__ __half g_xh[(size_t)BATCH * SEQ * HDIM];      // fp16 x
__device__ __half g_wh[3][(size_t)EMB * HDIM];           // fp16 weights
__device__ __half g_qkvh[3][(size_t)BATCH * SEQ * EMB];  // fp16 Q,K,V
__device__ float  g_p[(size_t)BATCH * SEQ * SEQ];        // fp32 scores
__device__ __half g_ph[(size_t)BATCH * SEQ * SEQ];       // fp16 probs

// ---------------------------------------------------------------------------
// PTX helpers
// ---------------------------------------------------------------------------
__device__ __forceinline__ void cp16(uint32_t dst, const void* src) {
    asm volatile("cp.async.ca.shared.global [%0], [%1], 16;" :: "r"(dst), "l"(src));
}
__device__ __forceinline__ void cp_commit() { asm volatile("cp.async.commit_group;"); }
template <int N>
__device__ __forceinline__ void cp_wait() { asm volatile("cp.async.wait_group %0;" :: "n"(N)); }

__device__ __forceinline__ void ldsm4(uint32_t* r, uint32_t addr) {
    asm volatile("ldmatrix.sync.aligned.m8n8.x4.shared.b16 {%0,%1,%2,%3}, [%4];"
                 : "=r"(r[0]), "=r"(r[1]), "=r"(r[2]), "=r"(r[3]) : "r"(addr));
}
__device__ __forceinline__ void ldsm4t(uint32_t* r, uint32_t addr) {
    asm volatile("ldmatrix.sync.aligned.m8n8.x4.trans.shared.b16 {%0,%1,%2,%3}, [%4];"
                 : "=r"(r[0]), "=r"(r[1]), "=r"(r[2]), "=r"(r[3]) : "r"(addr));
}
__device__ __forceinline__ void mma16(float* c, const uint32_t* a, const uint32_t* b) {
    asm volatile(
        "mma.sync.aligned.m16n8k16.row.col.f32.f16.f16.f32 "
        "{%0,%1,%2,%3}, {%4,%5,%6,%7}, {%8,%9}, {%0,%1,%2,%3};"
        : "+f"(c[0]), "+f"(c[1]), "+f"(c[2]), "+f"(c[3])
        : "r"(a[0]), "r"(a[1]), "r"(a[2]), "r"(a[3]), "r"(b[0]), "r"(b[1]));
}

// ---------------------------------------------------------------------------
// Kernel 0: single fp32 -> fp16 conversion pass for x + 3 weights.
// ---------------------------------------------------------------------------
#define XN4 ((BATCH * SEQ * HDIM) / 4)
#define WN4 ((EMB * HDIM) / 4)

__global__ void __launch_bounds__(NTHREADS)
cvt_kernel(const float4* __restrict__ xs, const float4* __restrict__ wq,
           const float4* __restrict__ wk, const float4* __restrict__ wv)
{
    int i = blockIdx.x * NTHREADS + threadIdx.x;
    const float4* src;
    __half* dst;
    int off;
    if (i < XN4)                { src = xs; dst = g_xh;    off = i; }
    else if (i < XN4 + WN4)     { src = wq; dst = g_wh[0]; off = i - XN4; }
    else if (i < XN4 + 2 * WN4) { src = wk; dst = g_wh[1]; off = i - XN4 - WN4; }
    else if (i < XN4 + 3 * WN4) { src = wv; dst = g_wh[2]; off = i - XN4 - 2 * WN4; }
    else return;
    float4 v = src[off];
    __half2 h0 = __floats2half2_rn(v.x, v.y);
    __half2 h1 = __floats2half2_rn(v.z, v.w);
    uint2 u;
    u.x = *reinterpret_cast<uint32_t*>(&h0);
    u.y = *reinterpret_cast<uint32_t*>(&h1);
    ((uint2*)dst)[off] = u;
}

// ---------------------------------------------------------------------------
// Shared fragment-address helpers (swizzled SW128: col16 ^= row&7)
// A tile rows 128 x 128B ; B tile rows 256 x 128B ; V tile rows 64 x 512B
// ---------------------------------------------------------------------------

// ---------------------------------------------------------------------------
// Kernel 1: QKV projection, NT fp16 GEMM + bias. grid (4, 64, 3).
// ---------------------------------------------------------------------------
__global__ void __launch_bounds__(NTHREADS, 1)
qkv_kernel(const float* __restrict__ bi0,
           const float* __restrict__ bi1,
           const float* __restrict__ bi2)
{
    extern __shared__ char dsm[];
    const uint32_t Abase = (uint32_t)__cvta_generic_to_shared(dsm);
    const uint32_t Bbase = Abase + NSTG * ATILEB;

    const int which = blockIdx.z;
    const __half* Ag = g_xh;
    const __half* Bg = g_wh[which];
    const float* bias = (which == 0) ? bi0 : (which == 1) ? bi1 : bi2;
    __half* out = g_qkvh[which];

    const int m0 = blockIdx.y * 128, n0 = blockIdx.x * 256;
    const int tid = threadIdx.x;
    const int warp = tid >> 5, lane = tid & 31;
    const int wm = warp & 1, wn = warp >> 1;         // wm: M half, wn: N quarter
    const int g = lane >> 2, tig = lane & 3;

    // cp.async loaders
    const int lr = tid >> 1;                          // 0..127
    const int lc = (tid & 1) * 4;                     // col16 base 0 or 4
    const __half* agp = Ag + (size_t)(m0 + lr) * HDIM;
    const __half* bgp0 = Bg + (size_t)(n0 + lr) * HDIM;
    const __half* bgp1 = Bg + (size_t)(n0 + lr + 128) * HDIM;
    const uint32_t lxor = (uint32_t)(lr & 7);

    // ldmatrix per-lane bases (R7-validated lane maps + swizzle)
    const uint32_t a_row  = (uint32_t)(wm * 64 + (lane & 15));          // + mi*16
    const uint32_t a_chi  = (uint32_t)(lane >> 4);
    const uint32_t a_xor  = (uint32_t)(lane & 7);
    const uint32_t b_row  = (uint32_t)(wn * 64 + (lane & 7) + ((lane >> 4) & 1) * 8); // + p*16
    const uint32_t b_chi  = (uint32_t)((lane >> 3) & 1);

    float acc[4][8][4];
#pragma unroll
    for (int i = 0; i < 4; i++)
#pragma unroll
        for (int j = 0; j < 8; j++)
#pragma unroll
            for (int k = 0; k < 4; k++) acc[i][j][k] = 0.f;

    auto pre = [&](int c, int s) {
        const __half* ap = agp + c * KC;
        const __half* bp0 = bgp0 + c * KC;
        const __half* bp1 = bgp1 + c * KC;
        const uint32_t as = Abase + s * ATILEB + lr * 128;
        const uint32_t bs0 = Bbase + s * BTILEB + lr * 128;
        const uint32_t bs1 = bs0 + 128 * 128;
#pragma unroll
        for (int j = 0; j < 4; j++) {
            const uint32_t c16 = lc + j;
            const uint32_t sw = (c16 ^ lxor) * 16;
            cp16(as + sw,  ap + c16 * 8);
            cp16(bs0 + sw, bp0 + c16 * 8);
            cp16(bs1 + sw, bp1 + c16 * 8);
        }
        cp_commit();
    };

    const int T = HDIM / KC;   // 16
    pre(0, 0); pre(1, 1); pre(2, 2);

    for (int t = 0; t < T; ++t) {
        if (t + 2 < T) cp_wait<2>(); else if (t + 1 < T) cp_wait<1>(); else cp_wait<0>();
        __syncthreads();
        if (t + 3 < T) pre(t + 3, (t + 3) & 3);

        const int s = t & 3;
        const uint32_t Ab = Abase + s * ATILEB;
        const uint32_t Bb = Bbase + s * BTILEB;
#pragma unroll
        for (int kk = 0; kk < 4; ++kk) {
            const uint32_t asw = ((kk * 2 + a_chi) ^ a_xor) * 16;
            const uint32_t bsw = ((kk * 2 + b_chi) ^ a_xor) * 16;
            uint32_t a[4][4];
#pragma unroll
            for (int mi = 0; mi < 4; ++mi)
                ldsm4(a[mi], Ab + (a_row + mi * 16) * 128 + asw);
            uint32_t b[4][4];
#pragma unroll
            for (int p = 0; p < 4; ++p)
                ldsm4(b[p], Bb + (b_row + p * 16) * 128 + bsw);
#pragma unroll
            for (int mi = 0; mi < 4; ++mi)
#pragma unroll
                for (int ni = 0; ni < 8; ++ni)
                    mma16(acc[mi][ni], a[mi], &b[ni >> 1][(ni & 1) * 2]);
        }
    }

    // epilogue: +bias, round to fp16, store
#pragma unroll
    for (int mi = 0; mi < 4; ++mi) {
        const int row = m0 + wm * 64 + mi * 16 + g;
#pragma unroll
        for (int ni = 0; ni < 8; ++ni) {
            const int col = n0 + wn * 64 + ni * 8 + 2 * tig;
            const float b0v = bias[col], b1v = bias[col + 1];
            __half2 h0 = __floats2half2_rn(acc[mi][ni][0] + b0v, acc[mi][ni][1] + b1v);
            __half2 h1 = __floats2half2_rn(acc[mi][ni][2] + b0v, acc[mi][ni][3] + b1v);
            *(__half2*)(out + (size_t)row * EMB + col)       = h0;
            *(__half2*)(out + (size_t)(row + 8) * EMB + col) = h1;
        }
    }
}

// ---------------------------------------------------------------------------
// Kernel 2: scores, NT fp16 GEMM, causal tiles only (2*nt <= qt), fp32 out.
// grid (8, 16, 4). CTA tile 128 x 256.
// ---------------------------------------------------------------------------
__global__ void __launch_bounds__(NTHREADS, 1)
scores_kernel()
{
    const int qt = blockIdx.y, nt = blockIdx.x;
    if (2 * nt > qt) return;
    const int b = blockIdx.z;

    extern __shared__ char dsm[];
    const uint32_t Abase = (uint32_t)__cvta_generic_to_shared(dsm);
    const uint32_t Bbase = Abase + NSTG * ATILEB;

    const __half* Q  = g_qkvh[0] + (size_t)b * SEQ * EMB;
    const __half* Km = g_qkvh[1] + (size_t)b * SEQ * EMB;
    float* P = g_p + (size_t)b * SEQ * SEQ;

    const int m0 = qt * 128, n0 = nt * 256;
    const int tid = threadIdx.x;
    const int warp = tid >> 5, lane = tid & 31;
    const int wm = warp & 1, wn = warp >> 1;
    const int g = lane >> 2, tig = lane & 3;

    const int lr = tid >> 1;
    const int lc = (tid & 1) * 4;
    const __half* agp = Q  + (size_t)(m0 + lr) * EMB;
    const __half* bgp0 = Km + (size_t)(n0 + lr) * EMB;
    const __half* bgp1 = Km + (size_t)(n0 + lr + 128) * EMB;
    const uint32_t lxor = (uint32_t)(lr & 7);

    const uint32_t a_row = (uint32_t)(wm * 64 + (lane & 15));
    const uint32_t a_chi = (uint32_t)(lane >> 4);
    const uint32_t a_xor = (uint32_t)(lane & 7);
    const uint32_t b_row = (uint32_t)(wn * 64 + (lane & 7) + ((lane >> 4) & 1) * 8);
    const uint32_t b_chi = (uint32_t)((lane >> 3) & 1);

    float acc[4][8][4];
#pragma unroll
    for (int i = 0; i < 4; i++)
#pragma unroll
        for (int j = 0; j < 8; j++)
#pragma unroll
            for (int k = 0; k < 4; k++) acc[i][j][k] = 0.f;

    auto pre = [&](int c, int s) {
        const __half* ap = agp + c * KC;
        const __half* bp0 = bgp0 + c * KC;
        const __half* bp1 = bgp1 + c * KC;
        const uint32_t as = Abase + s * ATILEB + lr * 128;
        const uint32_t bs0 = Bbase + s * BTILEB + lr * 128;
        const uint32_t bs1 = bs0 + 128 * 128;
#pragma unroll
        for (int j = 0; j < 4; j++) {
            const uint32_t c16 = lc + j;
            const uint32_t sw = (c16 ^ lxor) * 16;
            cp16(as + sw,  ap + c16 * 8);
            cp16(bs0 + sw, bp0 + c16 * 8);
            cp16(bs1 + sw, bp1 + c16 * 8);
        }
        cp_commit();
    };

    const int T = EMB / KC;   // 16
    pre(0, 0); pre(1, 1); pre(2, 2);

    for (int t = 0; t < T; ++t) {
        if (t + 2 < T) cp_wait<2>(); else if (t + 1 < T) cp_wait<1>(); else cp_wait<0>();
        __syncthreads();
        if (t + 3 < T) pre(t + 3, (t + 3) & 3);

        const int s = t & 3;
        const uint32_t Ab = Abase + s * ATILEB;
        const uint32_t Bb = Bbase + s * BTILEB;
#pragma unroll
        for (int kk = 0; kk < 4; ++kk) {
            const uint32_t asw = ((kk * 2 + a_chi) ^ a_xor) * 16;
            const uint32_t bsw = ((kk * 2 + b_chi) ^ a_xor) * 16;
            uint32_t a[4][4];
#pragma unroll
            for (int mi = 0; mi < 4; ++mi)
                ldsm4(a[mi], Ab + (a_row + mi * 16) * 128 + asw);
            uint32_t b[4][4];
#pragma unroll
            for (int p = 0; p < 4; ++p)
                ldsm4(b[p], Bb + (b_row + p * 16) * 128 + bsw);
#pragma unroll
            for (int mi = 0; mi < 4; ++mi)
#pragma unroll
                for (int ni = 0; ni < 8; ++ni)
                    mma16(acc[mi][ni], a[mi], &b[ni >> 1][(ni & 1) * 2]);
        }
    }

    const float scale = 0.03125f;  // 1/sqrt(1024)
#pragma unroll
    for (int mi = 0; mi < 4; ++mi) {
        const int row = m0 + wm * 64 + mi * 16 + g;
#pragma unroll
        for (int ni = 0; ni < 8; ++ni) {
            const int col = n0 + wn * 64 + ni * 8 + 2 * tig;
            float2 r0 = {acc[mi][ni][0] * scale, acc[mi][ni][1] * scale};
            float2 r1 = {acc[mi][ni][2] * scale, acc[mi][ni][3] * scale};
            *(float2*)(P + (size_t)row * SEQ + col)       = r0;
            *(float2*)(P + (size_t)(row + 8) * SEQ + col) = r1;
        }
    }
}

// ---------------------------------------------------------------------------
// Kernel 3: row softmax over [0..q]; fp16 probs out; zero-fill to tile end.
// ---------------------------------------------------------------------------
__global__ void __launch_bounds__(NTHREADS)
softmax_kernel()
{
    __shared__ float buf[SEQ];
    __shared__ float red[8];

    const int q = blockIdx.x & (SEQ - 1);
    const int b = blockIdx.x >> 11;
    const float* row = g_p + ((size_t)b * SEQ + q) * SEQ;
    __half* orow = g_ph + ((size_t)b * SEQ + q) * SEQ;
    const int n = q + 1;
    const int zend = ((q >> 7) + 1) << 7;
    const int tid = threadIdx.x;
    const int lane = tid & 31;
    const int wid = tid >> 5;

    float lmax = -1e30f;
    for (int i = tid; i < n; i += NTHREADS) {
        float v = row[i];
        buf[i] = v;
        lmax = fmaxf(lmax, v);
    }
#pragma unroll
    for (int off = 16; off; off >>= 1)
        lmax = fmaxf(lmax, __shfl_xor_sync(0xffffffffu, lmax, off));
    if (lane == 0) red[wid] = lmax;
    __syncthreads();
    float gmax = red[0];
#pragma unroll
    for (int w = 1; w < 8; w++) gmax = fmaxf(gmax, red[w]);
    __syncthreads();

    float lsum = 0.f;
    for (int i = tid; i < n; i += NTHREADS) {
        float e = __expf(buf[i] - gmax);
        buf[i] = e;
        lsum += e;
    }
#pragma unroll
    for (int off = 16; off; off >>= 1)
        lsum += __shfl_xor_sync(0xffffffffu, lsum, off);
    if (lane == 0) red[wid] = lsum;
    __syncthreads();
    float gsum = red[0];
#pragma unroll
    for (int w = 1; w < 8; w++) gsum += red[w];

    const float inv = 1.f / gsum;
    for (int i = tid; i < n; i += NTHREADS) orow[i] = __float2half_rn(buf[i] * inv);
    const __half hz = __float2half_rn(0.f);
    for (int i = n + tid; i < zend; i += NTHREADS) orow[i] = hz;
}

// ---------------------------------------------------------------------------
// Kernel 4: O = P @ V, NN fp16 GEMM (V via ldmatrix.trans), truncated K.
// grid (4, 16, 4). CTA tile 128 x 256.
// ---------------------------------------------------------------------------
__global__ void __launch_bounds__(NTHREADS, 1)
pv_kernel(float* __restrict__ out)
{
    extern __shared__ char dsm[];
    const uint32_t Abase = (uint32_t)__cvta_generic_to_shared(dsm);
    const uint32_t Vbase = Abase + NSTG * ATILEB;

    const int b  = blockIdx.z;
    const int mt = blockIdx.y;
    const int e0 = blockIdx.x * 256;

    const __half* P = g_ph + (size_t)b * SEQ * SEQ;
    const __half* V = g_qkvh[2] + (size_t)b * SEQ * EMB;

    const int m0 = mt * 128;
    const int tid = threadIdx.x;
    const int warp = tid >> 5, lane = tid & 31;
    const int wm = warp & 1, wn = warp >> 1;
    const int g = lane >> 2, tig = lane & 3;

    // A (P) loader: row = tid>>1, 4 col16
    const int lr = tid >> 1;
    const int lc = (tid & 1) * 4;
    const __half* agp = P + (size_t)(m0 + lr) * SEQ;
    const uint32_t lxor = (uint32_t)(lr & 7);
    // V loader: k-row = tid>>2 (0..63), 8 col16
    const int vr = tid >> 2;
    const int vcb = (tid & 3) * 8;
    const uint32_t vxor = (uint32_t)(vr & 7);

    // ldmatrix bases
    const uint32_t a_row = (uint32_t)(wm * 64 + (lane & 15));
    const uint32_t a_chi = (uint32_t)(lane >> 4);
    const uint32_t a_xor = (uint32_t)(lane & 7);
    // V trans map: row(in 16-k group)=lane&15, colgroup16 = lane>>4
    const uint32_t v_row = (uint32_t)(lane & 15);
    const uint32_t v_chi = (uint32_t)(lane >> 4);

    float acc[4][8][4];
#pragma unroll
    for (int i = 0; i < 4; i++)
#pragma unroll
        for (int j = 0; j < 8; j++)
#pragma unroll
            for (int k = 0; k < 4; k++) acc[i][j][k] = 0.f;

    auto pre = [&](int c, int s) {
        const __half* ap = agp + c * KC;
        const __half* vp = V + (size_t)(c * KC + vr) * EMB + e0;
        const uint32_t as = Abase + s * ATILEB + lr * 128;
        const uint32_t vs = Vbase + s * VTILEB + vr * 512;
#pragma unroll
        for (int j = 0; j < 4; j++) {
            const uint32_t c16 = lc + j;
            cp16(as + ((c16 ^ lxor) * 16), ap + c16 * 8);
        }
#pragma unroll
        for (int j = 0; j < 8; j++) {
            const uint32_t c16 = vcb + j;
            cp16(vs + ((c16 ^ vxor) * 16), vp + c16 * 8);
        }
        cp_commit();
    };

    const int T = (mt + 1) * 2;   // (mt+1)*128 / 64
    pre(0, 0);
    if (1 < T) pre(1, 1);
    if (2 < T) pre(2, 2);

    for (int t = 0; t < T; ++t) {
        if (t + 2 < T) cp_wait<2>(); else if (t + 1 < T) cp_wait<1>(); else cp_wait<0>();
        __syncthreads();
        if (t + 3 < T) pre(t + 3, (t + 3) & 3);

        const int s = t & 3;
        const uint32_t Ab = Abase + s * ATILEB;
        const uint32_t Vb = Vbase + s * VTILEB;
#pragma unroll
        for (int kk = 0; kk < 4; ++kk) {
            const uint32_t asw = ((kk * 2 + a_chi) ^ a_xor) * 16;
            uint32_t a[4][4];
#pragma unroll
            for (int mi = 0; mi < 4; ++mi)
                ldsm4(a[mi], Ab + (a_row + mi * 16) * 128 + asw);
            // V rows kk*16 + v_row, e-col16 = wn*8 + p*2 + v_chi, swizzle by row&7
            const uint32_t vrow = kk * 16 + v_row;
            const uint32_t vrx = vrow & 7;
            uint32_t b2[4][4];
#pragma unroll
            for (int p = 0; p < 4; ++p) {
                const uint32_t c16 = (uint32_t)(wn * 8 + p * 2) + v_chi;
                ldsm4t(b2[p], Vb + vrow * 512 + ((c16 ^ vrx) * 16));
            }
#pragma unroll
            for (int mi = 0; mi < 4; ++mi)
#pragma unroll
                for (int ni = 0; ni < 8; ++ni)
                    mma16(acc[mi][ni], a[mi], &b2[ni >> 1][(ni & 1) * 2]);
        }
    }

#pragma unroll
    for (int mi = 0; mi < 4; ++mi) {
        const int row = m0 + wm * 64 + mi * 16 + g;
#pragma unroll
        for (int ni = 0; ni < 8; ++ni) {
            const int col = e0 + wn * 64 + ni * 8 + 2 * tig;
            float2 r0 = {acc[mi][ni][0], acc[mi][ni][1]};
            float2 r1 = {acc[mi][ni][2], acc[mi][ni][3]};
            *(float2*)(out + ((size_t)b * SEQ + row) * EMB + col)     = r0;
            *(float2*)(out + ((size_t)b * SEQ + row + 8) * EMB + col) = r1;
        }
    }
}

// ---------------------------------------------------------------------------
extern "C" void kernel_launch(void* const* d_in, const int* in_sizes, int n_in,
                              void* d_out, int out_size)
{
    const float* xs = (const float*)d_in[0];
    const float* wq = (const float*)d_in[1];
    const float* bq = (const float*)d_in[2];
    const float* wk = (const float*)d_in[3];
    const float* bk = (const float*)d_in[4];
    const float* wv = (const float*)d_in[5];
    const float* bv = (const float*)d_in[6];
    float* out = (float*)d_out;

    const int GEMM_SMEM = NSTG * (ATILEB + BTILEB);    // 196608 B
    cudaFuncSetAttribute(qkv_kernel,    cudaFuncAttributeMaxDynamicSharedMemorySize, GEMM_SMEM);
    cudaFuncSetAttribute(scores_kernel, cudaFuncAttributeMaxDynamicSharedMemorySize, GEMM_SMEM);
    cudaFuncSetAttribute(pv_kernel,     cudaFuncAttributeMaxDynamicSharedMemorySize, GEMM_SMEM);

    // 0: fp16-convert x and all weights in one launch
    const int total4 = XN4 + 3 * WN4;
    cvt_kernel<<<(total4 + NTHREADS - 1) / NTHREADS, NTHREADS>>>(
        (const float4*)xs, (const float4*)wq, (const float4*)wk, (const float4*)wv);

    dim3 gqkv(EMB / 256, (BATCH * SEQ) / 128, 3);        // (4, 64, 3)
    qkv_kernel<<<gqkv, NTHREADS, GEMM_SMEM>>>(bq, bk, bv);

    dim3 gsc(SEQ / 256, SEQ / 128, BATCH);               // (8, 16, 4)
    scores_kernel<<<gsc, NTHREADS, GEMM_SMEM>>>();

    softmax_kernel<<<BATCH * SEQ, NTHREADS>>>();         // 8192 blocks

    dim3 gpv(EMB / 256, SEQ / 128, BATCH);               // (4, 16, 4)
    pv_kernel<<<gpv, NTHREADS, GEMM_SMEM>>>(out);
}